// round 7
// baseline (speedup 1.0000x reference)
#include <cuda_runtime.h>
#include <cuda_bf16.h>

// GAE backward affine suffix scan, fused prefix-length search.
// Inputs: rewards f32 [B,S], values f32 [B,S], dones i32 [B,S],
// mask i32 [B,S] (PREFIX mask: 1...1 0...0). Output: [advantages; returns].
//
//   L     = prefix length;  valid[t] = t < L
//   nd    = 1 - done
//   delta = r + GAMMA * values[t+1]*valid[t+1] * nd - v
//   g[t]  = valid[t] ? (delta + GAMMA*LAMBDA*nd * g[t+1]) : 0
//   adv = g ; ret = valid ? g + v : 0
//
// Mask traffic reduction: warp 0 probes mask at stride 64 (issued BEFORE the
// streaming loads so the probes sit at the front of the L1tex queue). The
// ballot localizes L to a 64-word window. Only the 8 threads whose chunks
// intersect the window read their actual mask words (one 256B line); all
// other threads derive validity statically (below window: valid, above:
// invalid). Saves ~64 MiB of the ~400 MiB traffic with ~1 exposed round.

#define GAMMA  0.999f
#define LAMBDA 0.95f
#define GL     (GAMMA * LAMBDA)
#define S_LEN  2048
#define TPB    256
#define EPT    8           // TPB*EPT == S_LEN
#define NW     (TPB / 32)  // 8 warps

__global__ __launch_bounds__(TPB)
void gae_kernel(const float* __restrict__ rewards,
                const float* __restrict__ values,
                const int*   __restrict__ dones,
                const int*   __restrict__ mask,
                float* __restrict__ adv_out,
                float* __restrict__ ret_out)
{
    const int tid  = threadIdx.x;
    const unsigned lane = tid & 31u;
    const unsigned warp = tid >> 5;

    const long long rowbase = (long long)blockIdx.x * S_LEN;
    const long long base    = rowbase + tid * EPT;

    // Phase 1: warp 0 issues the stride-64 mask probes FIRST (front of the
    // L1tex queue; resolves while the streaming loads below are in flight).
    int p1 = 0;
    if (warp == 0) p1 = __ldg(mask + rowbase + lane * 64);

    // Phase 2: coalesced streaming vector loads (touch-once -> evict-first).
    const float4* rp = reinterpret_cast<const float4*>(rewards + base);
    const float4* vp = reinterpret_cast<const float4*>(values  + base);
    const int4*   dp = reinterpret_cast<const int4*>(dones + base);
    float4 r4a = __ldcs(rp);     float4 r4b = __ldcs(rp + 1);
    float4 v4a = __ldcs(vp);     float4 v4b = __ldcs(vp + 1);
    int4   d4a = __ldcs(dp);     int4   d4b = __ldcs(dp + 1);

    // Phase 3: ballot -> window start w0 (L in (w0, w0+64]); broadcast.
    __shared__ int w0_sh;
    if (warp == 0) {
        unsigned b1 = __ballot_sync(0xffffffffu, p1 != 0);
        if (lane == 0) w0_sh = (b1 == 0u) ? -2048 : (int)(__popc(b1) - 1) * 64;
    }

    // Neighbor (t+1) value exchange (the sync also publishes w0_sh).
    __shared__ float nbr[TPB];
    nbr[tid] = v4a.x;
    __syncthreads();
    const int w0 = w0_sh;
    float v_next = (tid + 1 < TPB) ? nbr[tid + 1] : 0.f;

    const int t0 = tid * EPT;

    // Per-element validity:
    //   t0+EPT <= w0      -> chunk fully below window: all valid (w0 < L).
    //   t0 >= w0+64       -> at/above window end: all invalid (L <= w0+64).
    //   else              -> window chunk: read actual mask words.
    float mk[EPT], mn[EPT];
    if (t0 >= w0 && t0 < w0 + 64) {
        const int4* mp = reinterpret_cast<const int4*>(mask + base);
        int4 m4a = __ldg(mp);
        int4 m4b = __ldg(mp + 1);
        int  m8  = (t0 + EPT < S_LEN) ? __ldg(mask + base + EPT) : 0;
        int mw[EPT + 1] = {m4a.x, m4a.y, m4a.z, m4a.w,
                           m4b.x, m4b.y, m4b.z, m4b.w, m8};
#pragma unroll
        for (int j = 0; j < EPT; ++j) {
            mk[j] = (float)mw[j];
            mn[j] = (float)mw[j + 1];
        }
    } else {
        const float all = (t0 + EPT <= w0) ? 1.f : 0.f;  // below vs above
#pragma unroll
        for (int j = 0; j < EPT; ++j) { mk[j] = all; mn[j] = all; }
        // Below-window last element: t0+8 <= w0 < L -> mn stays 1. Correct.
    }

    float r[EPT]  = {r4a.x, r4a.y, r4a.z, r4a.w, r4b.x, r4b.y, r4b.z, r4b.w};
    float v[EPT]  = {v4a.x, v4a.y, v4a.z, v4a.w, v4b.x, v4b.y, v4b.z, v4b.w};
    float nd[EPT] = {1.f - (float)d4a.x, 1.f - (float)d4a.y,
                     1.f - (float)d4a.z, 1.f - (float)d4a.w,
                     1.f - (float)d4b.x, 1.f - (float)d4b.y,
                     1.f - (float)d4b.z, 1.f - (float)d4b.w};
    float nv[EPT] = {v[1], v[2], v[3], v[4], v[5], v[6], v[7], v_next};

    // Per-element affine transforms (c, d); invalid steps -> (0, 0).
    float c[EPT], d[EPT];
#pragma unroll
    for (int j = 0; j < EPT; ++j) {
        float nvj   = nv[j] * mn[j];              // zero past last valid step
        float delta = fmaf(GAMMA * nd[j], nvj, r[j]) - v[j];
        c[j] = mk[j] * GL * nd[j];
        d[j] = mk[j] * delta;
    }

    // Thread-local composition over the 8 steps (reverse time order).
    float A = 1.f, Bc = 0.f;
#pragma unroll
    for (int j = EPT - 1; j >= 0; --j) {
        Bc = fmaf(c[j], Bc, d[j]);
        A  = c[j] * A;
    }

    // Warp-level inclusive suffix scan (Kogge-Stone, shfl_down).
    float a = A, b = Bc;
#pragma unroll
    for (int off = 1; off < 32; off <<= 1) {
        float ra = __shfl_down_sync(0xffffffffu, a, off);
        float rb = __shfl_down_sync(0xffffffffu, b, off);
        if (lane + off < 32) {
            b = fmaf(a, rb, b);
            a = a * ra;
        }
    }
    // Exclusive suffix within warp: E_i = inclusive(i+1); identity at lane 31.
    float ea = __shfl_down_sync(0xffffffffu, a, 1);
    float eb = __shfl_down_sync(0xffffffffu, b, 1);
    if (lane == 31) { ea = 1.f; eb = 0.f; }

    // Cross-warp scan over NW=8 warp aggregates.
    __shared__ float wa[NW];
    __shared__ float wb[NW];
    __shared__ float wcarry[NW];
    if (lane == 0) { wa[warp] = a; wb[warp] = b; }
    __syncthreads();
    if (warp == 0 && lane < NW) {
        float aa = wa[lane], bb = wb[lane];
#pragma unroll
        for (int off = 1; off < NW; off <<= 1) {
            float ra = __shfl_down_sync(0x000000ffu, aa, off);
            float rb = __shfl_down_sync(0x000000ffu, bb, off);
            if (lane + off < NW) {
                bb = fmaf(aa, rb, bb);
                aa = aa * ra;
            }
        }
        float carry = __shfl_down_sync(0x000000ffu, bb, 1);
        if (lane == NW - 1) carry = 0.f;
        wcarry[lane] = carry;
    }
    __syncthreads();

    // Carry entering this thread's chunk from the right, then final pass.
    float g = fmaf(ea, wcarry[warp], eb);

    float adv[EPT], ret[EPT];
#pragma unroll
    for (int j = EPT - 1; j >= 0; --j) {
        g = fmaf(c[j], g, d[j]);   // exactly 0 where invalid (c=d=0)
        adv[j] = g;
        ret[j] = (mk[j] != 0.f) ? (g + v[j]) : 0.f;
    }

    float4* ap = reinterpret_cast<float4*>(adv_out + base);
    float4* tp = reinterpret_cast<float4*>(ret_out + base);
    __stcs(ap,     make_float4(adv[0], adv[1], adv[2], adv[3]));
    __stcs(ap + 1, make_float4(adv[4], adv[5], adv[6], adv[7]));
    __stcs(tp,     make_float4(ret[0], ret[1], ret[2], ret[3]));
    __stcs(tp + 1, make_float4(ret[4], ret[5], ret[6], ret[7]));
}

extern "C" void kernel_launch(void* const* d_in, const int* in_sizes, int n_in,
                              void* d_out, int out_size)
{
    const float* rewards = (const float*)d_in[0];
    const float* values  = (const float*)d_in[1];
    const int*   dones   = (const int*)d_in[2];
    const int*   mask    = (const int*)d_in[3];

    const int total = in_sizes[0];            // B * S
    const int B     = total / S_LEN;

    float* adv_out = (float*)d_out;
    float* ret_out = (float*)d_out + (long long)B * S_LEN;

    gae_kernel<<<B, TPB>>>(rewards, values, dones, mask, adv_out, ret_out);
}